// round 10
// baseline (speedup 1.0000x reference)
#include <cuda_runtime.h>
#include <cstdint>

#define NROWS 8192
#define NHID  64
#define NEMB  256
#define NSPLIT 16
#define KSPL  512          // K columns per CTA
#define NTILE 8            // 64-col tiles per CTA

__device__ float    g_h[NROWS * NHID];          // [row][d], tf32-rounded
__device__ float2   g_fsp[NROWS];               // (f_src+b, exp(f_src+b))
__device__ float2   g_fdp[NROWS];               // (f_dst,   exp(f_dst))
__device__ int      g_cnt[NROWS];
__device__ int      g_cq[NROWS * NSPLIT];       // per-row exclusive count before col 512*q
__device__ int      g_R[NROWS];
__device__ unsigned g_bits[NROWS * 256];        // row-major bitmask
__device__ float    g_part[(size_t)NSPLIT * NROWS * NHID];
__device__ float    g_Sp[NSPLIT * NROWS];

// ---------------- helpers ----------------
__device__ __forceinline__ float tf32r(float f) {
    unsigned o;
    asm("cvt.rna.tf32.f32 %0, %1;" : "=r"(o) : "f"(f));
    return __uint_as_float(o);
}
__device__ __forceinline__ void cpasync16(unsigned saddr, const void* gptr) {
    asm volatile("cp.async.cg.shared.global [%0], [%1], 16;" :: "r"(saddr), "l"(gptr));
}
__device__ __forceinline__ void cpasync8(unsigned saddr, const void* gptr) {
    asm volatile("cp.async.ca.shared.global [%0], [%1], 8;" :: "r"(saddr), "l"(gptr));
}
#define CP_COMMIT() asm volatile("cp.async.commit_group;")
#define CP_WAIT0()  asm volatile("cp.async.wait_group 0;")

__device__ __forceinline__ void mma_tf32(float (&c)[4], const float4& a, float b0, float b1) {
    asm("mma.sync.aligned.m16n8k8.row.col.f32.tf32.tf32.f32 "
        "{%0,%1,%2,%3},{%4,%5,%6,%7},{%8,%9},{%0,%1,%2,%3};"
        : "+f"(c[0]), "+f"(c[1]), "+f"(c[2]), "+f"(c[3])
        : "r"(__float_as_uint(a.x)), "r"(__float_as_uint(a.y)),
          "r"(__float_as_uint(a.z)), "r"(__float_as_uint(a.w)),
          "r"(__float_as_uint(b0)), "r"(__float_as_uint(b1)));
}

// ======================= K1: h (tf32-rounded), f tables =======================
__global__ void k_h(const float* __restrict__ x, const float* __restrict__ Ww,
                    const float* __restrict__ Wb, const float* __restrict__ a1,
                    const float* __restrict__ a2, const float* __restrict__ ab) {
    __shared__ float xs[16][NEMB];
    __shared__ float s1[16][2], s2[16][2];
    const int tid = threadIdx.x;
    const int r = tid >> 6, d = tid & 63;
    const int base = blockIdx.x * 16;

    {
        const float4* src = (const float4*)(x + (size_t)base * NEMB);
        float4* dst = (float4*)&xs[0][0];
        #pragma unroll
        for (int t = 0; t < 4; t++) dst[tid + t * 256] = __ldg(src + tid + t * 256);
    }
    __syncthreads();

    const float wb = Wb[d];
    float acc[4] = {wb, wb, wb, wb};
    #pragma unroll 4
    for (int k = 0; k < NEMB; k++) {
        const float wv = __ldg(Ww + k * NHID + d);
        acc[0] = fmaf(xs[r][k],      wv, acc[0]);
        acc[1] = fmaf(xs[r + 4][k],  wv, acc[1]);
        acc[2] = fmaf(xs[r + 8][k],  wv, acc[2]);
        acc[3] = fmaf(xs[r + 12][k], wv, acc[3]);
    }
    const float va1 = __ldg(a1 + d), va2 = __ldg(a2 + d);
    const int half = (tid >> 5) & 1;
    #pragma unroll
    for (int i = 0; i < 4; i++) {
        const int row = base + r + 4 * i;
        g_h[(size_t)row * NHID + d] = tf32r(acc[i]);
        float v1 = acc[i] * va1, v2 = acc[i] * va2;
        #pragma unroll
        for (int o = 16; o >= 1; o >>= 1) {
            v1 += __shfl_xor_sync(0xffffffffu, v1, o);
            v2 += __shfl_xor_sync(0xffffffffu, v2, o);
        }
        if ((tid & 31) == 0) { s1[r + 4 * i][half] = v1; s2[r + 4 * i][half] = v2; }
    }
    __syncthreads();
    if (tid < 16) {
        const int row = base + tid;
        float fs = s1[tid][0] + s1[tid][1] + ab[0];
        float fd = s2[tid][0] + s2[tid][1];
        g_fsp[row] = make_float2(fs, expf(fs));
        g_fdp[row] = make_float2(fd, expf(fd));
    }
}

// ======================= K2: row-major bitmask + counts + split prefixes =======================
__global__ void k_mask(const int* __restrict__ adj) {
    const int w = threadIdx.x >> 5, lane = threadIdx.x & 31;
    const int row = blockIdx.x * 8 + w;
    const int* p = adj + (size_t)row * NROWS;
    int c = 0;
    #pragma unroll 2
    for (int ch = 0; ch < 64; ch++) {
        if ((ch & 3) == 0 && lane == 0) g_cq[row * NSPLIT + (ch >> 2)] = c;
        unsigned b[4];
        #pragma unroll
        for (int q = 0; q < 4; q++)
            b[q] = __ballot_sync(0xffffffffu, __ldg(p + ch * 128 + q * 32 + lane) > 0);
        if (lane == 0)
            *(uint4*)(g_bits + (size_t)row * 256 + ch * 4) = make_uint4(b[0], b[1], b[2], b[3]);
        c += __popc(b[0]) + __popc(b[1]) + __popc(b[2]) + __popc(b[3]);
    }
    if (lane == 0) g_cnt[row] = c;
}

// ======================= K3: exclusive scan of counts =======================
__global__ void k_scan() {
    __shared__ int sums[256];
    const int t = threadIdx.x;
    const int base = t * 32;
    int tot = 0;
    #pragma unroll
    for (int k = 0; k < 32; k++) tot += g_cnt[base + k];
    sums[t] = tot;
    __syncthreads();
    #pragma unroll
    for (int off = 1; off < 256; off <<= 1) {
        int u = (t >= off) ? sums[t - off] : 0;
        __syncthreads();
        sums[t] += u;
        __syncthreads();
    }
    int run = sums[t] - tot;
    #pragma unroll
    for (int k = 0; k < 32; k++) { int c = g_cnt[base + k]; g_R[base + k] = run; run += c; }
}

// ======================= K4: main kernel (tf32 mma.sync) =======================
__device__ __forceinline__ float edgeE2(int rr, int rbhi, float2 arow) {
    const int hi = rr >> 13;
    float2 a = arow;
    if (hi != rbhi) a = __ldg(&g_fsp[hi]);     // rare 8192-crossing, predicated
    float2 bq = __ldg(&g_fdp[rr & (NROWS - 1)]);
    float s = a.x + bq.x;
    float u = 0.01f * s;
    float p = fmaf(fmaf(u, 0.5f, 1.0f), u, 1.0f);   // exp(u), |u|<=~0.05, err ~2e-5
    return (s >= 0.0f) ? a.y * bq.y : p;
}

// Phase A: fill A-fragment tile [64 rows][64 k]. Warp w owns rows 8w..8w+7.
__device__ __forceinline__ void phaseA(const uint2* __restrict__ sb, float* __restrict__ Af,
                                       int w, int lane, unsigned ml,
                                       int (&rank)[8], float (&sacc)[8]) {
    const int tl  = lane & 3;
    const int th2 = ((lane >> 2) & 1) << 1;
    const int kk0 = lane >> 3;
    const int x0  = kk0 << 2, x1 = (kk0 + 4) << 2;
    #pragma unroll
    for (int i = 0; i < 8; i++) {
        const int row = w * 8 + i;
        const uint2 bw = sb[row];
        const unsigned b0 = bw.x, b1 = bw.y;
        const int rb = rank[i];
        const int rbhi = rb >> 13;
        const float2 arow = __ldg(&g_fsp[rbhi]);   // uniform across warp, hoisted per row
        const int c0 = __popc(b0);
        rank[i] = rb + c0 + __popc(b1);
        float w0 = 0.f, w1 = 0.f;
        if ((b0 >> lane) & 1) { w0 = tf32r(edgeE2(rb + __popc(b0 & ml), rbhi, arow));      sacc[i] += w0; }
        if ((b1 >> lane) & 1) { w1 = tf32r(edgeE2(rb + c0 + __popc(b1 & ml), rbhi, arow)); sacc[i] += w1; }
        const int g = row & 7, hi = (row >> 3) & 1, mtile = row >> 4;
        const int base = g * 4 + tl;
        const int mb = mtile * 1024 + hi + th2;
        Af[mb + kk0 * 128 + ((base ^ x0) << 2)]       = w0;
        Af[mb + (kk0 + 4) * 128 + ((base ^ x1) << 2)] = w1;
    }
}

// Phase B: warp-tile (mi: 16 rows, nj: 32 cols, full 64 k)
__device__ __forceinline__ void phaseB(const float* __restrict__ Af, const float* __restrict__ hs,
                                       float (&acc)[4][4], int mi, int nj, int lane) {
    const int tl = lane & 3, gq = lane >> 2;
    #pragma unroll
    for (int kk = 0; kk < 8; kk++) {
        const int fl = lane ^ (kk << 2);
        const float4 a0 = *(const float4*)(Af + (mi * 8 + kk) * 128 + fl * 4);
        const float* hb = hs + (kk * 8 + tl) * 72 + nj * 32 + gq;
        #pragma unroll
        for (int n8 = 0; n8 < 4; n8++) {
            const float b0 = hb[n8 * 8];
            const float b1 = hb[n8 * 8 + 4 * 72];
            mma_tf32(acc[n8], a0, b0, b1);
        }
    }
}

// dynamic smem (floats): Af[2] 2x4096 | hs[2] 2x4608 | sbits[2] 2x128  = 70656 B
__global__ void __launch_bounds__(256, 3)
k_main() {
    extern __shared__ float dsm[];
    float* Af[2] = {dsm, dsm + 4096};
    float* hs[2] = {dsm + 8192, dsm + 8192 + 4608};
    uint2* sbits[2] = {(uint2*)(dsm + 17408), (uint2*)(dsm + 17536)};

    const int tid  = threadIdx.x;
    const int w    = tid >> 5;
    const int lane = tid & 31;
    const int split = blockIdx.x & (NSPLIT - 1);
    const int row0  = (blockIdx.x >> 4) * 64;
    const unsigned ml = (1u << lane) - 1u;
    const int mi = w >> 1, nj = w & 1;

    const unsigned hsa[2] = {
        (unsigned)__cvta_generic_to_shared(hs[0]),
        (unsigned)__cvta_generic_to_shared(hs[1]) };
    const unsigned sba[2] = {
        (unsigned)__cvta_generic_to_shared(sbits[0]),
        (unsigned)__cvta_generic_to_shared(sbits[1]) };

    int   rank[8];
    float sacc[8];
    #pragma unroll
    for (int i = 0; i < 8; i++) {
        const int row = row0 + w * 8 + i;
        rank[i] = __ldg(&g_R[row]) + __ldg(&g_cq[row * NSPLIT + split]);
        sacc[i] = 0.0f;
    }

    float acc[4][4];
    #pragma unroll
    for (int n = 0; n < 4; n++)
        #pragma unroll
        for (int p = 0; p < 4; p++) acc[n][p] = 0.0f;

    const int kbase = split * KSPL;
    #define LOAD_B(T, BUF) do {                                                 \
        const int kg = kbase + (T) * 64;                                        \
        _Pragma("unroll")                                                       \
        for (int c = 0; c < 4; c++) {                                           \
            const int id = tid + 256 * c;                                       \
            const int rr = id >> 4, oo = id & 15;                               \
            cpasync16(hsa[BUF] + rr * 288 + oo * 16,                            \
                      g_h + (size_t)(kg + rr) * 64 + oo * 4);                   \
        }                                                                       \
    } while (0)

    #define LOAD_BITS(T, BUF) do {                                              \
        if (tid < 64)                                                           \
            cpasync8(sba[BUF] + tid * 8,                                        \
                     g_bits + (size_t)(row0 + tid) * 256 + split * 16 + 2 * (T)); \
    } while (0)

    // -------- prologue --------
    LOAD_B(0, 0);
    LOAD_BITS(0, 0);
    LOAD_BITS(1, 1);
    CP_COMMIT();
    CP_WAIT0();
    __syncthreads();
    phaseA(sbits[0], Af[0], w, lane, ml, rank, sacc);
    __syncthreads();

    // -------- main loop: NTILE tiles of 64 cols --------
    for (int t = 0; t < NTILE; t++) {
        const int cur = t & 1, nxt = cur ^ 1;
        if (t + 1 < NTILE) LOAD_B(t + 1, nxt);
        if (t + 2 < NTILE) LOAD_BITS(t + 2, cur);
        CP_COMMIT();
        phaseB(Af[cur], hs[cur], acc, mi, nj, lane);
        if (t + 1 < NTILE)
            phaseA(sbits[nxt], Af[nxt], w, lane, ml, rank, sacc);
        CP_WAIT0();
        __syncthreads();
    }

    // ---- denominators ----
    #pragma unroll
    for (int i = 0; i < 8; i++) {
        float sv = sacc[i];
        #pragma unroll
        for (int o = 16; o >= 1; o >>= 1) sv += __shfl_xor_sync(0xffffffffu, sv, o);
        if (lane == 0) g_Sp[split * NROWS + row0 + w * 8 + i] = sv;
    }

    // ---- direct numerator write (no kh combine) ----
    {
        const int tl = lane & 3, gq = lane >> 2;
        const int grow = row0 + mi * 16 + gq;
        float* dst = g_part + ((size_t)split * NROWS + grow) * 64 + nj * 32 + tl * 2;
        #pragma unroll
        for (int n8 = 0; n8 < 4; n8++) {
            *(float2*)(dst + n8 * 8)            = make_float2(acc[n8][0], acc[n8][1]);
            *(float2*)(dst + 8 * 64 + n8 * 8)   = make_float2(acc[n8][2], acc[n8][3]);
        }
    }
}

// ======================= K5: combine 16 K-splits + softmax divide + elu =======================
__global__ void k_comb(float* __restrict__ out) {
    const int idx = blockIdx.x * 256 + threadIdx.x;   // float4 index over [8192][16]
    const int row = idx >> 4;
    const int c4  = idx & 15;
    float4 v = make_float4(0.f, 0.f, 0.f, 0.f);
    float S = 0.f;
    #pragma unroll 4
    for (int s = 0; s < NSPLIT; s++) {
        const float4 p = *(const float4*)(g_part + ((size_t)s * NROWS + row) * NHID + c4 * 4);
        v.x += p.x; v.y += p.y; v.z += p.z; v.w += p.w;
        S += g_Sp[s * NROWS + row];
    }
    const float sinv = 1.0f / S;
    float o[4] = {v.x * sinv, v.y * sinv, v.z * sinv, v.w * sinv};
    #pragma unroll
    for (int c = 0; c < 4; c++) o[c] = (o[c] > 0.0f) ? o[c] : expm1f(o[c]);
    *(float4*)(out + (size_t)row * NHID + c4 * 4) = make_float4(o[0], o[1], o[2], o[3]);
}

extern "C" void kernel_launch(void* const* d_in, const int* in_sizes, int n_in,
                              void* d_out, int out_size) {
    (void)in_sizes; (void)n_in; (void)out_size;
    const float* x   = (const float*)d_in[0];
    const int*   adj = (const int*)d_in[1];
    const float* Ww  = (const float*)d_in[2];
    const float* Wb  = (const float*)d_in[3];
    const float* a1  = (const float*)d_in[4];
    const float* a2  = (const float*)d_in[5];
    const float* ab  = (const float*)d_in[6];
    float* out = (float*)d_out;

    cudaFuncSetAttribute(k_main, cudaFuncAttributeMaxDynamicSharedMemorySize, 70656);

    k_h   <<<NROWS / 16, 256>>>(x, Ww, Wb, a1, a2, ab);
    k_mask<<<NROWS / 8, 256>>>(adj);
    k_scan<<<1, 256>>>();
    k_main<<<128 * NSPLIT, 256, 70656>>>();
    k_comb<<<NROWS * NHID / 1024, 256>>>(out);
}

// round 11
// speedup vs baseline: 1.1867x; 1.1867x over previous
#include <cuda_runtime.h>
#include <cuda_fp16.h>
#include <cstdint>

#define NROWS 8192
#define NHID  64
#define NEMB  256
#define NSPLIT 16
#define KSPL  512
#define NTILE 8

__device__ __half   g_hp[4096 * 128];           // packed: row r=(k>>3)*4+(k&3), half idx r*128+d*2+((k>>2)&1)
__device__ float2   g_fsp[NROWS];               // (f_src+b, exp(f_src+b))
__device__ float2   g_fdp[NROWS];               // (f_dst,   exp(f_dst))
__device__ int      g_cnt[NROWS];
__device__ int      g_cq[NROWS * NSPLIT];
__device__ int      g_R[NROWS];
__device__ unsigned g_bits[NROWS * 256];
__device__ float    g_part[(size_t)NSPLIT * NROWS * NHID];
__device__ float    g_Sp[NSPLIT * NROWS];

// ---------------- helpers ----------------
__device__ __forceinline__ float tf32r(float f) {
    unsigned o;
    asm("cvt.rna.tf32.f32 %0, %1;" : "=r"(o) : "f"(f));
    return __uint_as_float(o);
}
__device__ __forceinline__ void cpasync16(unsigned saddr, const void* gptr) {
    asm volatile("cp.async.cg.shared.global [%0], [%1], 16;" :: "r"(saddr), "l"(gptr));
}
__device__ __forceinline__ void cpasync8(unsigned saddr, const void* gptr) {
    asm volatile("cp.async.ca.shared.global [%0], [%1], 8;" :: "r"(saddr), "l"(gptr));
}
#define CP_COMMIT() asm volatile("cp.async.commit_group;")
#define CP_WAIT0()  asm volatile("cp.async.wait_group 0;")

__device__ __forceinline__ void mma_tf32(float (&c)[4], const float4& a, float b0, float b1) {
    asm("mma.sync.aligned.m16n8k8.row.col.f32.tf32.tf32.f32 "
        "{%0,%1,%2,%3},{%4,%5,%6,%7},{%8,%9},{%0,%1,%2,%3};"
        : "+f"(c[0]), "+f"(c[1]), "+f"(c[2]), "+f"(c[3])
        : "r"(__float_as_uint(a.x)), "r"(__float_as_uint(a.y)),
          "r"(__float_as_uint(a.z)), "r"(__float_as_uint(a.w)),
          "r"(__float_as_uint(b0)), "r"(__float_as_uint(b1)));
}

// ======================= K1: h (packed fp16), f tables =======================
__global__ void k_h(const float* __restrict__ x, const float* __restrict__ Ww,
                    const float* __restrict__ Wb, const float* __restrict__ a1,
                    const float* __restrict__ a2, const float* __restrict__ ab) {
    __shared__ float xs[16][NEMB];
    __shared__ float s1[16][2], s2[16][2];
    const int tid = threadIdx.x;
    const int r = tid >> 6, d = tid & 63;
    const int base = blockIdx.x * 16;

    {
        const float4* src = (const float4*)(x + (size_t)base * NEMB);
        float4* dst = (float4*)&xs[0][0];
        #pragma unroll
        for (int t = 0; t < 4; t++) dst[tid + t * 256] = __ldg(src + tid + t * 256);
    }
    __syncthreads();

    const float wb = Wb[d];
    float acc[4] = {wb, wb, wb, wb};
    #pragma unroll 4
    for (int k = 0; k < NEMB; k++) {
        const float wv = __ldg(Ww + k * NHID + d);
        acc[0] = fmaf(xs[r][k],      wv, acc[0]);
        acc[1] = fmaf(xs[r + 4][k],  wv, acc[1]);
        acc[2] = fmaf(xs[r + 8][k],  wv, acc[2]);
        acc[3] = fmaf(xs[r + 12][k], wv, acc[3]);
    }
    const float va1 = __ldg(a1 + d), va2 = __ldg(a2 + d);
    const int half_ = (tid >> 5) & 1;
    #pragma unroll
    for (int i = 0; i < 4; i++) {
        const int row = base + r + 4 * i;           // this is k in the GEMM's K dim
        const int pr = (row >> 3) * 4 + (row & 3);
        g_hp[(size_t)pr * 128 + d * 2 + ((row >> 2) & 1)] = __float2half_rn(acc[i]);
        float v1 = acc[i] * va1, v2 = acc[i] * va2;
        #pragma unroll
        for (int o = 16; o >= 1; o >>= 1) {
            v1 += __shfl_xor_sync(0xffffffffu, v1, o);
            v2 += __shfl_xor_sync(0xffffffffu, v2, o);
        }
        if ((tid & 31) == 0) { s1[r + 4 * i][half_] = v1; s2[r + 4 * i][half_] = v2; }
    }
    __syncthreads();
    if (tid < 16) {
        const int row = base + tid;
        float fs = s1[tid][0] + s1[tid][1] + ab[0];
        float fd = s2[tid][0] + s2[tid][1];
        g_fsp[row] = make_float2(fs, expf(fs));
        g_fdp[row] = make_float2(fd, expf(fd));
    }
}

// ======================= K2: row-major bitmask + counts + split prefixes =======================
__global__ void k_mask(const int* __restrict__ adj) {
    const int w = threadIdx.x >> 5, lane = threadIdx.x & 31;
    const int row = blockIdx.x * 8 + w;
    const int* p = adj + (size_t)row * NROWS;
    int c = 0;
    #pragma unroll 2
    for (int ch = 0; ch < 64; ch++) {
        if ((ch & 3) == 0 && lane == 0) g_cq[row * NSPLIT + (ch >> 2)] = c;
        unsigned b[4];
        #pragma unroll
        for (int q = 0; q < 4; q++)
            b[q] = __ballot_sync(0xffffffffu, __ldg(p + ch * 128 + q * 32 + lane) > 0);
        if (lane == 0)
            *(uint4*)(g_bits + (size_t)row * 256 + ch * 4) = make_uint4(b[0], b[1], b[2], b[3]);
        c += __popc(b[0]) + __popc(b[1]) + __popc(b[2]) + __popc(b[3]);
    }
    if (lane == 0) g_cnt[row] = c;
}

// ======================= K3: exclusive scan of counts =======================
__global__ void k_scan() {
    __shared__ int sums[256];
    const int t = threadIdx.x;
    const int base = t * 32;
    int tot = 0;
    #pragma unroll
    for (int k = 0; k < 32; k++) tot += g_cnt[base + k];
    sums[t] = tot;
    __syncthreads();
    #pragma unroll
    for (int off = 1; off < 256; off <<= 1) {
        int u = (t >= off) ? sums[t - off] : 0;
        __syncthreads();
        sums[t] += u;
        __syncthreads();
    }
    int run = sums[t] - tot;
    #pragma unroll
    for (int k = 0; k < 32; k++) { int c = g_cnt[base + k]; g_R[base + k] = run; run += c; }
}

// ======================= K4: main kernel =======================
__device__ __forceinline__ float edgeE2(int rr, int rbhi, float2 arow) {
    const int hi = rr >> 13;
    float2 a = arow;
    if (hi != rbhi) a = __ldg(&g_fsp[hi]);
    float2 bq = __ldg(&g_fdp[rr & (NROWS - 1)]);
    float s = a.x + bq.x;
    float u = 0.01f * s;
    float p = fmaf(fmaf(u, 0.5f, 1.0f), u, 1.0f);
    return (s >= 0.0f) ? a.y * bq.y : p;
}

__device__ __forceinline__ void phaseA(const uint2* __restrict__ sb, float* __restrict__ Af,
                                       int w, int lane, unsigned ml,
                                       int (&rank)[8], float (&sacc)[8]) {
    const int tl  = lane & 3;
    const int th2 = ((lane >> 2) & 1) << 1;
    const int kk0 = lane >> 3;
    const int x0  = kk0 << 2, x1 = (kk0 + 4) << 2;
    #pragma unroll
    for (int i = 0; i < 8; i++) {
        const int row = w * 8 + i;
        const uint2 bw = sb[row];
        const unsigned b0 = bw.x, b1 = bw.y;
        const int rb = rank[i];
        const int rbhi = rb >> 13;
        const float2 arow = __ldg(&g_fsp[rbhi]);
        const int c0 = __popc(b0);
        rank[i] = rb + c0 + __popc(b1);
        float w0 = 0.f, w1 = 0.f;
        if ((b0 >> lane) & 1) { w0 = tf32r(edgeE2(rb + __popc(b0 & ml), rbhi, arow));      sacc[i] += w0; }
        if ((b1 >> lane) & 1) { w1 = tf32r(edgeE2(rb + c0 + __popc(b1 & ml), rbhi, arow)); sacc[i] += w1; }
        const int g = row & 7, hi = (row >> 3) & 1, mtile = row >> 4;
        const int base = g * 4 + tl;
        const int mb = mtile * 1024 + hi + th2;
        Af[mb + kk0 * 128 + ((base ^ x0) << 2)]       = w0;
        Af[mb + (kk0 + 4) * 128 + ((base ^ x1) << 2)] = w1;
    }
}

// Phase B: A fp32 frags, B packed half2 (b0,b1) -> one LDS.32 + cvt
__device__ __forceinline__ void phaseB(const float* __restrict__ Af, const __half2* __restrict__ hs,
                                       float (&acc)[4][4], int mi, int nj, int lane) {
    const int tl = lane & 3, gq = lane >> 2;
    #pragma unroll
    for (int kk = 0; kk < 8; kk++) {
        const int fl = lane ^ (kk << 2);
        const float4 a0 = *(const float4*)(Af + (mi * 8 + kk) * 128 + fl * 4);
        const __half2* hb = hs + (kk * 4 + tl) * 72 + nj * 32 + gq;
        #pragma unroll
        for (int n8 = 0; n8 < 4; n8++) {
            const __half2 hv = hb[n8 * 8];
            mma_tf32(acc[n8], a0, __low2float(hv), __high2float(hv));
        }
    }
}

// smem bytes: Af[2] 2x16384 | hs[2] 2x9216 | sbits[2] 2x512  = 52224
__global__ void __launch_bounds__(256, 3)
k_main() {
    extern __shared__ char dsm[];
    float*  Af[2] = {(float*)dsm, (float*)(dsm + 16384)};
    __half2* hs[2] = {(__half2*)(dsm + 32768), (__half2*)(dsm + 41984)};
    uint2*  sbits[2] = {(uint2*)(dsm + 51200), (uint2*)(dsm + 51712)};

    const int tid  = threadIdx.x;
    const int w    = tid >> 5;
    const int lane = tid & 31;
    const int split = blockIdx.x & (NSPLIT - 1);
    const int row0  = (blockIdx.x >> 4) * 64;
    const unsigned ml = (1u << lane) - 1u;
    const int mi = w >> 1, nj = w & 1;

    const unsigned hsa[2] = {
        (unsigned)__cvta_generic_to_shared(hs[0]),
        (unsigned)__cvta_generic_to_shared(hs[1]) };
    const unsigned sba[2] = {
        (unsigned)__cvta_generic_to_shared(sbits[0]),
        (unsigned)__cvta_generic_to_shared(sbits[1]) };

    int   rank[8];
    float sacc[8];
    #pragma unroll
    for (int i = 0; i < 8; i++) {
        const int row = row0 + w * 8 + i;
        rank[i] = __ldg(&g_R[row]) + __ldg(&g_cq[row * NSPLIT + split]);
        sacc[i] = 0.0f;
    }

    float acc[4][4];
    #pragma unroll
    for (int n = 0; n < 4; n++)
        #pragma unroll
        for (int p = 0; p < 4; p++) acc[n][p] = 0.0f;

    const int kbase = split * KSPL;
    // tile t covers g_hp rows [ (kbase + t*64)/2 , +32 ), each row 256B -> smem stride 288B
    #define LOAD_B(T, BUF) do {                                                 \
        const size_t rb = (size_t)((kbase + (T) * 64) >> 1);                    \
        _Pragma("unroll")                                                       \
        for (int c = 0; c < 2; c++) {                                           \
            const int id = tid + 256 * c;                                       \
            const int rr = id >> 4, oo = id & 15;                               \
            cpasync16(hsa[BUF] + rr * 288 + oo * 16,                            \
                      (const char*)g_hp + (rb + rr) * 256 + oo * 16);           \
        }                                                                       \
    } while (0)

    #define LOAD_BITS(T, BUF) do {                                              \
        if (tid < 64)                                                           \
            cpasync8(sba[BUF] + tid * 8,                                        \
                     g_bits + (size_t)(row0 + tid) * 256 + split * 16 + 2 * (T)); \
    } while (0)

    // -------- prologue --------
    LOAD_B(0, 0);
    LOAD_BITS(0, 0);
    LOAD_BITS(1, 1);
    CP_COMMIT();
    CP_WAIT0();
    __syncthreads();
    phaseA(sbits[0], Af[0], w, lane, ml, rank, sacc);
    __syncthreads();

    // -------- main loop --------
    for (int t = 0; t < NTILE; t++) {
        const int cur = t & 1, nxt = cur ^ 1;
        if (t + 1 < NTILE) LOAD_B(t + 1, nxt);
        if (t + 2 < NTILE) LOAD_BITS(t + 2, cur);
        CP_COMMIT();
        phaseB(Af[cur], hs[cur], acc, mi, nj, lane);
        if (t + 1 < NTILE)
            phaseA(sbits[nxt], Af[nxt], w, lane, ml, rank, sacc);
        CP_WAIT0();
        __syncthreads();
    }

    // ---- denominators ----
    #pragma unroll
    for (int i = 0; i < 8; i++) {
        float sv = sacc[i];
        #pragma unroll
        for (int o = 16; o >= 1; o >>= 1) sv += __shfl_xor_sync(0xffffffffu, sv, o);
        if (lane == 0) g_Sp[split * NROWS + row0 + w * 8 + i] = sv;
    }

    // ---- numerator partials ----
    {
        const int tl = lane & 3, gq = lane >> 2;
        const int grow = row0 + mi * 16 + gq;
        float* dst = g_part + ((size_t)split * NROWS + grow) * 64 + nj * 32 + tl * 2;
        #pragma unroll
        for (int n8 = 0; n8 < 4; n8++) {
            *(float2*)(dst + n8 * 8)          = make_float2(acc[n8][0], acc[n8][1]);
            *(float2*)(dst + 8 * 64 + n8 * 8) = make_float2(acc[n8][2], acc[n8][3]);
        }
    }
}

// ======================= K5: combine splits + softmax divide + elu =======================
__global__ void k_comb(float* __restrict__ out) {
    const int idx = blockIdx.x * 256 + threadIdx.x;
    const int row = idx >> 4;
    const int c4  = idx & 15;
    float4 v = make_float4(0.f, 0.f, 0.f, 0.f);
    float S = 0.f;
    #pragma unroll 4
    for (int s = 0; s < NSPLIT; s++) {
        const float4 p = *(const float4*)(g_part + ((size_t)s * NROWS + row) * NHID + c4 * 4);
        v.x += p.x; v.y += p.y; v.z += p.z; v.w += p.w;
        S += g_Sp[s * NROWS + row];
    }
    const float sinv = 1.0f / S;
    float o[4] = {v.x * sinv, v.y * sinv, v.z * sinv, v.w * sinv};
    #pragma unroll
    for (int c = 0; c < 4; c++) o[c] = (o[c] > 0.0f) ? o[c] : expm1f(o[c]);
    *(float4*)(out + (size_t)row * NHID + c4 * 4) = make_float4(o[0], o[1], o[2], o[3]);
}

extern "C" void kernel_launch(void* const* d_in, const int* in_sizes, int n_in,
                              void* d_out, int out_size) {
    (void)in_sizes; (void)n_in; (void)out_size;
    const float* x   = (const float*)d_in[0];
    const int*   adj = (const int*)d_in[1];
    const float* Ww  = (const float*)d_in[2];
    const float* Wb  = (const float*)d_in[3];
    const float* a1  = (const float*)d_in[4];
    const float* a2  = (const float*)d_in[5];
    const float* ab  = (const float*)d_in[6];
    float* out = (float*)d_out;

    cudaFuncSetAttribute(k_main, cudaFuncAttributeMaxDynamicSharedMemorySize, 52224);

    k_h   <<<NROWS / 16, 256>>>(x, Ww, Wb, a1, a2, ab);
    k_mask<<<NROWS / 8, 256>>>(adj);
    k_scan<<<1, 256>>>();
    k_main<<<128 * NSPLIT, 256, 52224>>>();
    k_comb<<<NROWS * NHID / 1024, 256>>>(out);
}

// round 12
// speedup vs baseline: 1.4571x; 1.2279x over previous
#include <cuda_runtime.h>
#include <cuda_fp16.h>
#include <cstdint>

#define NROWS 8192
#define NHID  64
#define NEMB  256
#define NSPLIT 16
#define KSPL  512
#define NTILE 8

__device__ __half   g_hp[4096 * 128];    // row pr=(k>>4)*8+((k&15)>>1): half2[d]=(h[k_even],h[k_odd])
__device__ float2   g_fsp[NROWS];        // (f_src+b, exp(f_src+b))
__device__ float2   g_fdp[NROWS];        // (f_dst,   exp(f_dst))
__device__ int      g_cnt[NROWS];
__device__ int      g_cq[NROWS * NSPLIT];
__device__ int      g_R[NROWS];
__device__ unsigned g_bits[NROWS * 256];
__device__ float    g_part[(size_t)NSPLIT * NROWS * NHID];
__device__ float    g_Sp[NSPLIT * NROWS];

// ---------------- helpers ----------------
__device__ __forceinline__ void cpasync16(unsigned saddr, const void* gptr) {
    asm volatile("cp.async.cg.shared.global [%0], [%1], 16;" :: "r"(saddr), "l"(gptr));
}
__device__ __forceinline__ void cpasync8(unsigned saddr, const void* gptr) {
    asm volatile("cp.async.ca.shared.global [%0], [%1], 8;" :: "r"(saddr), "l"(gptr));
}
#define CP_COMMIT() asm volatile("cp.async.commit_group;")
#define CP_WAIT0()  asm volatile("cp.async.wait_group 0;")

__device__ __forceinline__ void mma_f16(float (&c)[4], unsigned a0, unsigned a1,
                                        unsigned a2, unsigned a3, unsigned b0, unsigned b1) {
    asm("mma.sync.aligned.m16n8k16.row.col.f32.f16.f16.f32 "
        "{%0,%1,%2,%3},{%4,%5,%6,%7},{%8,%9},{%0,%1,%2,%3};"
        : "+f"(c[0]), "+f"(c[1]), "+f"(c[2]), "+f"(c[3])
        : "r"(a0), "r"(a1), "r"(a2), "r"(a3), "r"(b0), "r"(b1));
}

// ======================= K1: fused mask-scan + h/f-tables =======================
// blocks [0,1024): bitmask+counts for 8 rows each; blocks [1024,1536): h for 16 rows each
__global__ void k_pre(const float* __restrict__ x, const float* __restrict__ Ww,
                      const float* __restrict__ Wb, const float* __restrict__ a1,
                      const float* __restrict__ a2, const float* __restrict__ ab,
                      const int* __restrict__ adj) {
    __shared__ float xs[16][NEMB];
    __shared__ float s1[16][2], s2[16][2];
    const int tid = threadIdx.x;

    if (blockIdx.x < 1024) {
        // ---------------- mask part ----------------
        const int w = tid >> 5, lane = tid & 31;
        const int row = blockIdx.x * 8 + w;
        const int* p = adj + (size_t)row * NROWS;
        int c = 0;
        #pragma unroll 2
        for (int ch = 0; ch < 64; ch++) {
            if ((ch & 3) == 0 && lane == 0) g_cq[row * NSPLIT + (ch >> 2)] = c;
            unsigned b[4];
            #pragma unroll
            for (int q = 0; q < 4; q++)
                b[q] = __ballot_sync(0xffffffffu, __ldg(p + ch * 128 + q * 32 + lane) > 0);
            if (lane == 0)
                *(uint4*)(g_bits + (size_t)row * 256 + ch * 4) = make_uint4(b[0], b[1], b[2], b[3]);
            c += __popc(b[0]) + __popc(b[1]) + __popc(b[2]) + __popc(b[3]);
        }
        if (lane == 0) g_cnt[row] = c;
        return;
    }

    // ---------------- h part ----------------
    const int bid = blockIdx.x - 1024;
    const int r = tid >> 6, d = tid & 63;
    const int base = bid * 16;
    {
        const float4* src = (const float4*)(x + (size_t)base * NEMB);
        float4* dst = (float4*)&xs[0][0];
        #pragma unroll
        for (int t = 0; t < 4; t++) dst[tid + t * 256] = __ldg(src + tid + t * 256);
    }
    __syncthreads();

    const float wb = Wb[d];
    float acc[4] = {wb, wb, wb, wb};
    #pragma unroll 4
    for (int k = 0; k < NEMB; k++) {
        const float wv = __ldg(Ww + k * NHID + d);
        acc[0] = fmaf(xs[r][k],      wv, acc[0]);
        acc[1] = fmaf(xs[r + 4][k],  wv, acc[1]);
        acc[2] = fmaf(xs[r + 8][k],  wv, acc[2]);
        acc[3] = fmaf(xs[r + 12][k], wv, acc[3]);
    }
    const float va1 = __ldg(a1 + d), va2 = __ldg(a2 + d);
    const int half_ = (tid >> 5) & 1;
    #pragma unroll
    for (int i = 0; i < 4; i++) {
        const int k = base + r + 4 * i;                     // GEMM K index
        const int pr = (k >> 4) * 8 + ((k & 15) >> 1);
        g_hp[(size_t)pr * 128 + d * 2 + (k & 1)] = __float2half_rn(acc[i]);
        float v1 = acc[i] * va1, v2 = acc[i] * va2;
        #pragma unroll
        for (int o = 16; o >= 1; o >>= 1) {
            v1 += __shfl_xor_sync(0xffffffffu, v1, o);
            v2 += __shfl_xor_sync(0xffffffffu, v2, o);
        }
        if ((tid & 31) == 0) { s1[r + 4 * i][half_] = v1; s2[r + 4 * i][half_] = v2; }
    }
    __syncthreads();
    if (tid < 16) {
        const int row = base + tid;
        float fs = s1[tid][0] + s1[tid][1] + ab[0];
        float fd = s2[tid][0] + s2[tid][1];
        g_fsp[row] = make_float2(fs, expf(fs));
        g_fdp[row] = make_float2(fd, expf(fd));
    }
}

// ======================= K3: exclusive scan of counts =======================
__global__ void k_scan() {
    __shared__ int sums[256];
    const int t = threadIdx.x;
    const int base = t * 32;
    int tot = 0;
    #pragma unroll
    for (int k = 0; k < 32; k++) tot += g_cnt[base + k];
    sums[t] = tot;
    __syncthreads();
    #pragma unroll
    for (int off = 1; off < 256; off <<= 1) {
        int u = (t >= off) ? sums[t - off] : 0;
        __syncthreads();
        sums[t] += u;
        __syncthreads();
    }
    int run = sums[t] - tot;
    #pragma unroll
    for (int k = 0; k < 32; k++) { int c = g_cnt[base + k]; g_R[base + k] = run; run += c; }
}

// ======================= K4: main kernel (fp16 mma.sync) =======================
__device__ __forceinline__ float edgeE2(int rr, int rbhi, float2 arow) {
    const int hi = rr >> 13;
    float2 a = arow;
    if (hi != rbhi) a = __ldg(&g_fsp[hi]);
    float2 bq = __ldg(&g_fdp[rr & (NROWS - 1)]);
    float s = a.x + bq.x;
    float u = 0.01f * s;
    float p = fmaf(fmaf(u, 0.5f, 1.0f), u, 1.0f);
    return (s >= 0.0f) ? a.y * bq.y : p;
}

// Phase A: dense fp16 A tile [64 rows][64 k], ldmatrix swizzle. Warp w owns rows 8w..8w+7.
__device__ __forceinline__ void phaseA(const uint2* __restrict__ sb, unsigned short* __restrict__ Af,
                                       int w, int lane, unsigned ml,
                                       int (&rank)[8], float (&sacc)[8]) {
    const int ch  = lane >> 3;        // 0..3
    const int lo  = lane & 7;
    #pragma unroll
    for (int i = 0; i < 8; i++) {
        const int row = w * 8 + i;
        const uint2 bw = sb[row];
        const unsigned b0 = bw.x, b1 = bw.y;
        const int rb = rank[i];
        const int rbhi = rb >> 13;
        const float2 arow = __ldg(&g_fsp[rbhi]);
        const int c0 = __popc(b0);
        rank[i] = rb + c0 + __popc(b1);
        unsigned short h0 = 0, h1 = 0;
        if ((b0 >> lane) & 1) {
            const __half hh = __float2half_rn(edgeE2(rb + __popc(b0 & ml), rbhi, arow));
            h0 = __half_as_ushort(hh); sacc[i] += __half2float(hh);
        }
        if ((b1 >> lane) & 1) {
            const __half hh = __float2half_rn(edgeE2(rb + c0 + __popc(b1 & ml), rbhi, arow));
            h1 = __half_as_ushort(hh); sacc[i] += __half2float(hh);
        }
        const int swz = row & 7;
        unsigned short* rp = Af + row * 64 + lo;
        rp[((ch ^ swz) << 3)]       = h0;   // col = lane
        rp[(((ch + 4) ^ swz) << 3)] = h1;   // col = lane + 32
    }
}

// Phase B: A via ldmatrix.x4 (swizzled), B = raw half2 pairs from hs.
__device__ __forceinline__ void phaseB(unsigned afa, const __half2* __restrict__ hb,
                                       float (&acc)[4][4], int mi, int nj, int lane) {
    const int tl = lane & 3, gq = lane >> 2;
    const int r  = mi * 16 + (lane & 15);
    const int hk = lane >> 4;
    const unsigned abase = afa + r * 128;
    const int rs = r & 7;
    #pragma unroll
    for (int s = 0; s < 4; s++) {
        unsigned a0, a1, a2, a3;
        const unsigned addr = abase + ((unsigned)(((s * 2 + hk) ^ rs)) << 4);
        asm volatile("ldmatrix.sync.aligned.m8n8.x4.shared.b16 {%0,%1,%2,%3}, [%4];"
                     : "=r"(a0), "=r"(a1), "=r"(a2), "=r"(a3) : "r"(addr));
        const __half2* hp = hb + s * 8 * 72;
        const int d = nj * 32 + gq;
        #pragma unroll
        for (int n8 = 0; n8 < 4; n8++) {
            const unsigned b0 = *(const unsigned*)(hp + tl * 72 + d + n8 * 8);
            const unsigned b1 = *(const unsigned*)(hp + (tl + 4) * 72 + d + n8 * 8);
            mma_f16(acc[n8], a0, a1, a2, a3, b0, b1);
        }
    }
}

// smem bytes: Af[2] 2x8192 | hs[2] 2x9216 | sbits[2] 2x512 = 35840
__global__ void __launch_bounds__(256, 3)
k_main() {
    extern __shared__ char dsm[];
    unsigned short* Af[2] = {(unsigned short*)dsm, (unsigned short*)(dsm + 8192)};
    __half2* hs[2] = {(__half2*)(dsm + 16384), (__half2*)(dsm + 25600)};
    uint2*  sbits[2] = {(uint2*)(dsm + 34816), (uint2*)(dsm + 35328)};

    const int tid  = threadIdx.x;
    const int w    = tid >> 5;
    const int lane = tid & 31;
    const int split = blockIdx.x & (NSPLIT - 1);
    const int row0  = (blockIdx.x >> 4) * 64;
    const unsigned ml = (1u << lane) - 1u;
    const int mi = w >> 1, nj = w & 1;

    const unsigned afa[2] = {
        (unsigned)__cvta_generic_to_shared(Af[0]),
        (unsigned)__cvta_generic_to_shared(Af[1]) };
    const unsigned hsa[2] = {
        (unsigned)__cvta_generic_to_shared(hs[0]),
        (unsigned)__cvta_generic_to_shared(hs[1]) };
    const unsigned sba[2] = {
        (unsigned)__cvta_generic_to_shared(sbits[0]),
        (unsigned)__cvta_generic_to_shared(sbits[1]) };

    int   rank[8];
    float sacc[8];
    #pragma unroll
    for (int i = 0; i < 8; i++) {
        const int row = row0 + w * 8 + i;
        rank[i] = __ldg(&g_R[row]) + __ldg(&g_cq[row * NSPLIT + split]);
        sacc[i] = 0.0f;
    }

    float acc[4][4];
    #pragma unroll
    for (int n = 0; n < 4; n++)
        #pragma unroll
        for (int p = 0; p < 4; p++) acc[n][p] = 0.0f;

    const int kbase = split * KSPL;
    #define LOAD_B(T, BUF) do {                                                 \
        const size_t rb = (size_t)((kbase + (T) * 64) >> 1);                    \
        _Pragma("unroll")                                                       \
        for (int c = 0; c < 2; c++) {                                           \
            const int id = tid + 256 * c;                                       \
            const int rr = id >> 4, oo = id & 15;                               \
            cpasync16(hsa[BUF] + rr * 288 + oo * 16,                            \
                      (const char*)g_hp + (rb + rr) * 256 + oo * 16);           \
        }                                                                       \
    } while (0)

    #define LOAD_BITS(T, BUF) do {                                              \
        if (tid < 64)                                                           \
            cpasync8(sba[BUF] + tid * 8,                                        \
                     g_bits + (size_t)(row0 + tid) * 256 + split * 16 + 2 * (T)); \
    } while (0)

    // -------- prologue --------
    LOAD_B(0, 0);
    LOAD_BITS(0, 0);
    LOAD_BITS(1, 1);
    CP_COMMIT();
    CP_WAIT0();
    __syncthreads();
    phaseA(sbits[0], Af[0], w, lane, ml, rank, sacc);
    __syncthreads();

    // -------- main loop --------
    for (int t = 0; t < NTILE; t++) {
        const int cur = t & 1, nxt = cur ^ 1;
        if (t + 1 < NTILE) LOAD_B(t + 1, nxt);
        if (t + 2 < NTILE) LOAD_BITS(t + 2, cur);
        CP_COMMIT();
        phaseB(afa[cur], hs[cur], acc, mi, nj, lane);
        if (t + 1 < NTILE)
            phaseA(sbits[nxt], Af[nxt], w, lane, ml, rank, sacc);
        CP_WAIT0();
        __syncthreads();
    }

    // ---- denominators ----
    #pragma unroll
    for (int i = 0; i < 8; i++) {
        float sv = sacc[i];
        #pragma unroll
        for (int o = 16; o >= 1; o >>= 1) sv += __shfl_xor_sync(0xffffffffu, sv, o);
        if (lane == 0) g_Sp[split * NROWS + row0 + w * 8 + i] = sv;
    }

    // ---- numerator partials ----
    {
        const int tl = lane & 3, gq = lane >> 2;
        const int grow = row0 + mi * 16 + gq;
        float* dst = g_part + ((size_t)split * NROWS + grow) * 64 + nj * 32 + tl * 2;
        #pragma unroll
        for (int n8 = 0; n8 < 4; n8++) {
            *(float2*)(dst + n8 * 8)          = make_float2(acc[n8][0], acc[n8][1]);
            *(float2*)(dst + 8 * 64 + n8 * 8) = make_float2(acc[n8][2], acc[n8][3]);
        }
    }
}

// ======================= K5: combine splits + softmax divide + elu =======================
__global__ void k_comb(float* __restrict__ out) {
    const int idx = blockIdx.x * 256 + threadIdx.x;
    const int row = idx >> 4;
    const int c4  = idx & 15;
    float4 v = make_float4(0.f, 0.f, 0.f, 0.f);
    float S = 0.f;
    #pragma unroll 4
    for (int s = 0; s < NSPLIT; s++) {
        const float4 p = *(const float4*)(g_part + ((size_t)s * NROWS + row) * NHID + c4 * 4);
        v.x += p.x; v.y += p.y; v.z += p.z; v.w += p.w;
        S += g_Sp[s * NROWS + row];
    }
    const float sinv = 1.0f / S;
    float o[4] = {v.x * sinv, v.y * sinv, v.z * sinv, v.w * sinv};
    #pragma unroll
    for (int c = 0; c < 4; c++) o[c] = (o[c] > 0.0f) ? o[c] : expm1f(o[c]);
    *(float4*)(out + (size_t)row * NHID + c4 * 4) = make_float4(o[0], o[1], o[2], o[3]);
}

extern "C" void kernel_launch(void* const* d_in, const int* in_sizes, int n_in,
                              void* d_out, int out_size) {
    (void)in_sizes; (void)n_in; (void)out_size;
    const float* x   = (const float*)d_in[0];
    const int*   adj = (const int*)d_in[1];
    const float* Ww  = (const float*)d_in[2];
    const float* Wb  = (const float*)d_in[3];
    const float* a1  = (const float*)d_in[4];
    const float* a2  = (const float*)d_in[5];
    const float* ab  = (const float*)d_in[6];
    float* out = (float*)d_out;

    cudaFuncSetAttribute(k_main, cudaFuncAttributeMaxDynamicSharedMemorySize, 35840);

    k_pre <<<1536, 256>>>(x, Ww, Wb, a1, a2, ab, adj);
    k_scan<<<1, 256>>>();
    k_main<<<128 * NSPLIT, 256, 35840>>>();
    k_comb<<<NROWS * NHID / 1024, 256>>>(out);
}

// round 13
// speedup vs baseline: 1.4683x; 1.0077x over previous
#include <cuda_runtime.h>
#include <cuda_fp16.h>
#include <cstdint>

#define NROWS 8192
#define NHID  64
#define NEMB  256
#define NSPLIT 8
#define NCQ   16
#define KSPL  1024
#define NTILE 16

__device__ __half   g_hp[4096 * 128];    // row pr=(k>>4)*8+((k&15)>>1): half2[d]=(h[k_even],h[k_odd])
__device__ float2   g_fsp[NROWS];        // (f_src+b, exp(f_src+b))
__device__ float2   g_fdp[NROWS];        // (f_dst,   exp(f_dst))
__device__ int      g_cnt[NROWS];
__device__ int      g_cq[NROWS * NCQ];   // prefix count before col 512*q
__device__ int      g_R[NROWS];
__device__ unsigned g_bits[NROWS * 256];
__device__ float    g_part[(size_t)NSPLIT * NROWS * NHID];
__device__ float    g_Sp[NSPLIT * NROWS];

// ---------------- helpers ----------------
__device__ __forceinline__ void cpasync16(unsigned saddr, const void* gptr) {
    asm volatile("cp.async.cg.shared.global [%0], [%1], 16;" :: "r"(saddr), "l"(gptr));
}
__device__ __forceinline__ void cpasync8(unsigned saddr, const void* gptr) {
    asm volatile("cp.async.ca.shared.global [%0], [%1], 8;" :: "r"(saddr), "l"(gptr));
}
#define CP_COMMIT() asm volatile("cp.async.commit_group;")
#define CP_WAIT0()  asm volatile("cp.async.wait_group 0;")

__device__ __forceinline__ void mma_f16(float (&c)[4], unsigned a0, unsigned a1,
                                        unsigned a2, unsigned a3, unsigned b0, unsigned b1) {
    asm("mma.sync.aligned.m16n8k16.row.col.f32.f16.f16.f32 "
        "{%0,%1,%2,%3},{%4,%5,%6,%7},{%8,%9},{%0,%1,%2,%3};"
        : "+f"(c[0]), "+f"(c[1]), "+f"(c[2]), "+f"(c[3])
        : "r"(a0), "r"(a1), "r"(a2), "r"(a3), "r"(b0), "r"(b1));
}

// ======================= K1: fused mask-scan + h/f-tables =======================
__global__ void k_pre(const float* __restrict__ x, const float* __restrict__ Ww,
                      const float* __restrict__ Wb, const float* __restrict__ a1,
                      const float* __restrict__ a2, const float* __restrict__ ab,
                      const int* __restrict__ adj) {
    __shared__ float xs[16][NEMB];
    __shared__ float s1[16][2], s2[16][2];
    const int tid = threadIdx.x;

    if (blockIdx.x < 1024) {
        const int w = tid >> 5, lane = tid & 31;
        const int row = blockIdx.x * 8 + w;
        const int* p = adj + (size_t)row * NROWS;
        int c = 0;
        #pragma unroll 2
        for (int ch = 0; ch < 64; ch++) {
            if ((ch & 3) == 0 && lane == 0) g_cq[row * NCQ + (ch >> 2)] = c;
            unsigned b[4];
            #pragma unroll
            for (int q = 0; q < 4; q++)
                b[q] = __ballot_sync(0xffffffffu, __ldg(p + ch * 128 + q * 32 + lane) > 0);
            if (lane == 0)
                *(uint4*)(g_bits + (size_t)row * 256 + ch * 4) = make_uint4(b[0], b[1], b[2], b[3]);
            c += __popc(b[0]) + __popc(b[1]) + __popc(b[2]) + __popc(b[3]);
        }
        if (lane == 0) g_cnt[row] = c;
        return;
    }

    const int bid = blockIdx.x - 1024;
    const int r = tid >> 6, d = tid & 63;
    const int base = bid * 16;
    {
        const float4* src = (const float4*)(x + (size_t)base * NEMB);
        float4* dst = (float4*)&xs[0][0];
        #pragma unroll
        for (int t = 0; t < 4; t++) dst[tid + t * 256] = __ldg(src + tid + t * 256);
    }
    __syncthreads();

    const float wb = Wb[d];
    float acc[4] = {wb, wb, wb, wb};
    #pragma unroll 4
    for (int k = 0; k < NEMB; k++) {
        const float wv = __ldg(Ww + k * NHID + d);
        acc[0] = fmaf(xs[r][k],      wv, acc[0]);
        acc[1] = fmaf(xs[r + 4][k],  wv, acc[1]);
        acc[2] = fmaf(xs[r + 8][k],  wv, acc[2]);
        acc[3] = fmaf(xs[r + 12][k], wv, acc[3]);
    }
    const float va1 = __ldg(a1 + d), va2 = __ldg(a2 + d);
    const int half_ = (tid >> 5) & 1;
    #pragma unroll
    for (int i = 0; i < 4; i++) {
        const int k = base + r + 4 * i;
        const int pr = (k >> 4) * 8 + ((k & 15) >> 1);
        g_hp[(size_t)pr * 128 + d * 2 + (k & 1)] = __float2half_rn(acc[i]);
        float v1 = acc[i] * va1, v2 = acc[i] * va2;
        #pragma unroll
        for (int o = 16; o >= 1; o >>= 1) {
            v1 += __shfl_xor_sync(0xffffffffu, v1, o);
            v2 += __shfl_xor_sync(0xffffffffu, v2, o);
        }
        if ((tid & 31) == 0) { s1[r + 4 * i][half_] = v1; s2[r + 4 * i][half_] = v2; }
    }
    __syncthreads();
    if (tid < 16) {
        const int row = base + tid;
        float fs = s1[tid][0] + s1[tid][1] + ab[0];
        float fd = s2[tid][0] + s2[tid][1];
        g_fsp[row] = make_float2(fs, expf(fs));
        g_fdp[row] = make_float2(fd, expf(fd));
    }
}

// ======================= K3: exclusive scan of counts =======================
__global__ void k_scan() {
    __shared__ int sums[256];
    const int t = threadIdx.x;
    const int base = t * 32;
    int tot = 0;
    #pragma unroll
    for (int k = 0; k < 32; k++) tot += g_cnt[base + k];
    sums[t] = tot;
    __syncthreads();
    #pragma unroll
    for (int off = 1; off < 256; off <<= 1) {
        int u = (t >= off) ? sums[t - off] : 0;
        __syncthreads();
        sums[t] += u;
        __syncthreads();
    }
    int run = sums[t] - tot;
    #pragma unroll
    for (int k = 0; k < 32; k++) { int c = g_cnt[base + k]; g_R[base + k] = run; run += c; }
}

// ======================= K4: main kernel (fp16 mma.sync) =======================
__device__ __forceinline__ float edgeE2(int rr, int rbhi, float2 arow) {
    const int hi = rr >> 13;
    float2 a = arow;
    if (hi != rbhi) a = __ldg(&g_fsp[hi]);
    float2 bq = __ldg(&g_fdp[rr & (NROWS - 1)]);
    float s = a.x + bq.x;
    float u = 0.01f * s;
    float p = fmaf(fmaf(u, 0.5f, 1.0f), u, 1.0f);
    return (s >= 0.0f) ? a.y * bq.y : p;
}

// Phase A: lane handles adjacent cols (2l, 2l+1); one conflict-free STS.32 per row.
__device__ __forceinline__ void phaseA(const uint2* __restrict__ sb, unsigned short* __restrict__ Af,
                                       int w, int lane, unsigned mA, unsigned mB, int sh,
                                       int (&rank)[8], float (&sacc)[8]) {
    const int ch = lane >> 2;             // (2l)>>3
    const int lo = (2 * lane) & 7;
    #pragma unroll
    for (int i = 0; i < 8; i++) {
        const int row = w * 8 + i;
        const uint2 bw = sb[row];
        const unsigned b0 = bw.x, b1 = bw.y;
        const int rb = rank[i];
        const int rbhi = rb >> 13;
        const float2 arow = __ldg(&g_fsp[rbhi]);
        rank[i] = rb + __popc(b0) + __popc(b1);
        const int below = __popc(b0 & mA) + __popc(b1 & mB);
        const unsigned ul = (lane < 16) ? b0 : b1;
        const unsigned bb = (ul >> sh) & 3u;
        unsigned short h0 = 0, h1 = 0;
        if (bb & 1u) {
            const __half hh = __float2half_rn(edgeE2(rb + below, rbhi, arow));
            h0 = __half_as_ushort(hh); sacc[i] += __half2float(hh);
        }
        if (bb & 2u) {
            const __half hh = __float2half_rn(edgeE2(rb + below + (int)(bb & 1u), rbhi, arow));
            h1 = __half_as_ushort(hh); sacc[i] += __half2float(hh);
        }
        const int swz = row & 7;
        *(unsigned*)(Af + row * 64 + ((ch ^ swz) << 3) + lo) =
            (unsigned)h0 | ((unsigned)h1 << 16);
    }
}

// Phase B: A via ldmatrix.x4 (swizzled), B = raw half2 pairs from hs.
__device__ __forceinline__ void phaseB(unsigned afa, const __half2* __restrict__ hb,
                                       float (&acc)[4][4], int mi, int nj, int lane) {
    const int tl = lane & 3, gq = lane >> 2;
    const int r  = mi * 16 + (lane & 15);
    const int hk = lane >> 4;
    const unsigned abase = afa + r * 128;
    const int rs = r & 7;
    #pragma unroll
    for (int s = 0; s < 4; s++) {
        unsigned a0, a1, a2, a3;
        const unsigned addr = abase + ((unsigned)(((s * 2 + hk) ^ rs)) << 4);
        asm volatile("ldmatrix.sync.aligned.m8n8.x4.shared.b16 {%0,%1,%2,%3}, [%4];"
                     : "=r"(a0), "=r"(a1), "=r"(a2), "=r"(a3) : "r"(addr));
        const __half2* hp = hb + s * 8 * 72;
        const int d = nj * 32 + gq;
        #pragma unroll
        for (int n8 = 0; n8 < 4; n8++) {
            const unsigned b0 = *(const unsigned*)(hp + tl * 72 + d + n8 * 8);
            const unsigned b1 = *(const unsigned*)(hp + (tl + 4) * 72 + d + n8 * 8);
            mma_f16(acc[n8], a0, a1, a2, a3, b0, b1);
        }
    }
}

// smem bytes: Af[2] 2x8192 | hs[2] 2x9216 | sbits[2] 2x512 = 35840
__global__ void __launch_bounds__(256, 3)
k_main() {
    extern __shared__ char dsm[];
    unsigned short* Af[2] = {(unsigned short*)dsm, (unsigned short*)(dsm + 8192)};
    __half2* hs[2] = {(__half2*)(dsm + 16384), (__half2*)(dsm + 25600)};
    uint2*  sbits[2] = {(uint2*)(dsm + 34816), (uint2*)(dsm + 35328)};

    const int tid  = threadIdx.x;
    const int w    = tid >> 5;
    const int lane = tid & 31;
    const int split = blockIdx.x & (NSPLIT - 1);
    const int row0  = (blockIdx.x >> 3) * 64;
    const int mi = w >> 1, nj = w & 1;

    // loop-invariant Phase-A lane constants
    const int sh = 2 * (lane & 15);
    unsigned mA, mB;
    if (lane < 16) { mA = (1u << sh) - 1u; mB = 0u; }
    else           { mA = 0xFFFFFFFFu;     mB = (1u << sh) - 1u; }

    const unsigned afa[2] = {
        (unsigned)__cvta_generic_to_shared(Af[0]),
        (unsigned)__cvta_generic_to_shared(Af[1]) };
    const unsigned hsa[2] = {
        (unsigned)__cvta_generic_to_shared(hs[0]),
        (unsigned)__cvta_generic_to_shared(hs[1]) };
    const unsigned sba[2] = {
        (unsigned)__cvta_generic_to_shared(sbits[0]),
        (unsigned)__cvta_generic_to_shared(sbits[1]) };

    int   rank[8];
    float sacc[8];
    #pragma unroll
    for (int i = 0; i < 8; i++) {
        const int row = row0 + w * 8 + i;
        rank[i] = __ldg(&g_R[row]) + __ldg(&g_cq[row * NCQ + 2 * split]);
        sacc[i] = 0.0f;
    }

    float acc[4][4];
    #pragma unroll
    for (int n = 0; n < 4; n++)
        #pragma unroll
        for (int p = 0; p < 4; p++) acc[n][p] = 0.0f;

    const int kbase = split * KSPL;
    #define LOAD_B(T, BUF) do {                                                 \
        const size_t rb = (size_t)((kbase + (T) * 64) >> 1);                    \
        _Pragma("unroll")                                                       \
        for (int c = 0; c < 2; c++) {                                           \
            const int id = tid + 256 * c;                                       \
            const int rr = id >> 4, oo = id & 15;                               \
            cpasync16(hsa[BUF] + rr * 288 + oo * 16,                            \
                      (const char*)g_hp + (rb + rr) * 256 + oo * 16);           \
        }                                                                       \
    } while (0)

    #define LOAD_BITS(T, BUF) do {                                              \
        if (tid < 64)                                                           \
            cpasync8(sba[BUF] + tid * 8,                                        \
                     g_bits + (size_t)(row0 + tid) * 256 + split * 32 + 2 * (T)); \
    } while (0)

    // -------- prologue --------
    LOAD_B(0, 0);
    LOAD_BITS(0, 0);
    LOAD_BITS(1, 1);
    CP_COMMIT();
    CP_WAIT0();
    __syncthreads();
    phaseA(sbits[0], Af[0], w, lane, mA, mB, sh, rank, sacc);
    __syncthreads();

    // -------- main loop --------
    for (int t = 0; t < NTILE; t++) {
        const int cur = t & 1, nxt = cur ^ 1;
        if (t + 1 < NTILE) LOAD_B(t + 1, nxt);
        if (t + 2 < NTILE) LOAD_BITS(t + 2, cur);
        CP_COMMIT();
        phaseB(afa[cur], hs[cur], acc, mi, nj, lane);
        if (t + 1 < NTILE)
            phaseA(sbits[nxt], Af[nxt], w, lane, mA, mB, sh, rank, sacc);
        CP_WAIT0();
        __syncthreads();
    }

    // ---- denominators ----
    #pragma unroll
    for (int i = 0; i < 8; i++) {
        float sv = sacc[i];
        #pragma unroll
        for (int o = 16; o >= 1; o >>= 1) sv += __shfl_xor_sync(0xffffffffu, sv, o);
        if (lane == 0) g_Sp[split * NROWS + row0 + w * 8 + i] = sv;
    }

    // ---- numerator partials ----
    {
        const int tl = lane & 3, gq = lane >> 2;
        const int grow = row0 + mi * 16 + gq;
        float* dst = g_part + ((size_t)split * NROWS + grow) * 64 + nj * 32 + tl * 2;
        #pragma unroll
        for (int n8 = 0; n8 < 4; n8++) {
            *(float2*)(dst + n8 * 8)          = make_float2(acc[n8][0], acc[n8][1]);
            *(float2*)(dst + 8 * 64 + n8 * 8) = make_float2(acc[n8][2], acc[n8][3]);
        }
    }
}

// ======================= K5: combine splits + softmax divide + elu =======================
__global__ void k_comb(float* __restrict__ out) {
    const int idx = blockIdx.x * 256 + threadIdx.x;
    const int row = idx >> 4;
    const int c4  = idx & 15;
    float4 v = make_float4(0.f, 0.f, 0.f, 0.f);
    float S = 0.f;
    #pragma unroll
    for (int s = 0; s < NSPLIT; s++) {
        const float4 p = *(const float4*)(g_part + ((size_t)s * NROWS + row) * NHID + c4 * 4);
        v.x += p.x; v.y += p.y; v.z += p.z; v.w += p.w;
        S += g_Sp[s * NROWS + row];
    }
    const float sinv = 1.0f / S;
    float o[4] = {v.x * sinv, v.y * sinv, v.z * sinv, v.w * sinv};
    #pragma unroll
    for (int c = 0; c < 4; c++) o[c] = (o[c] > 0.0f) ? o[c] : expm1f(o[c]);
    *(float4*)(out + (size_t)row * NHID + c4 * 4) = make_float4(o[0], o[1], o[2], o[3]);
}

extern "C" void kernel_launch(void* const* d_in, const int* in_sizes, int n_in,
                              void* d_out, int out_size) {
    (void)in_sizes; (void)n_in; (void)out_size;
    const float* x   = (const float*)d_in[0];
    const int*   adj = (const int*)d_in[1];
    const float* Ww  = (const float*)d_in[2];
    const float* Wb  = (const float*)d_in[3];
    const float* a1  = (const float*)d_in[4];
    const float* a2  = (const float*)d_in[5];
    const float* ab  = (const float*)d_in[6];
    float* out = (float*)d_out;

    cudaFuncSetAttribute(k_main, cudaFuncAttributeMaxDynamicSharedMemorySize, 35840);

    k_pre <<<1536, 256>>>(x, Ww, Wb, a1, a2, ab, adj);
    k_scan<<<1, 256>>>();
    k_main<<<128 * NSPLIT, 256, 35840>>>();
    k_comb<<<NROWS * NHID / 1024, 256>>>(out);
}

// round 15
// speedup vs baseline: 1.6090x; 1.0958x over previous
#include <cuda_runtime.h>
#include <cuda_fp16.h>
#include <cstdint>

#define NROWS 8192
#define NHID  64
#define NEMB  256
#define NSPLIT 8
#define NCQ   16
#define KSPL  1024
#define NTILE 16

__device__ __align__(16) __half   g_hp[4096 * 128];
__device__ __align__(16) unsigned short g_E[(size_t)NROWS * NROWS]; // [mtile*128+kt][4096] fragment images
__device__ float2   g_fsp[NROWS];
__device__ float2   g_fdp[NROWS];
__device__ int      g_cnt[NROWS];
__device__ int      g_cq[NROWS * NCQ];
__device__ int      g_R[NROWS];
__device__ __align__(16) unsigned g_bits[NROWS * 256];
__device__ float    g_part[(size_t)NSPLIT * NROWS * NHID];
__device__ float    g_Sp[NSPLIT * NROWS];

// ---------------- helpers ----------------
__device__ __forceinline__ void cpasync16(unsigned saddr, const void* gptr) {
    asm volatile("cp.async.cg.shared.global [%0], [%1], 16;" :: "r"(saddr), "l"(gptr));
}
#define CP_COMMIT() asm volatile("cp.async.commit_group;")

__device__ __forceinline__ void mma_f16(float (&c)[4], unsigned a0, unsigned a1,
                                        unsigned a2, unsigned a3, unsigned b0, unsigned b1) {
    asm("mma.sync.aligned.m16n8k16.row.col.f32.f16.f16.f32 "
        "{%0,%1,%2,%3},{%4,%5,%6,%7},{%8,%9},{%0,%1,%2,%3};"
        : "+f"(c[0]), "+f"(c[1]), "+f"(c[2]), "+f"(c[3])
        : "r"(a0), "r"(a1), "r"(a2), "r"(a3), "r"(b0), "r"(b1));
}

// ======================= K1: fused mask-scan + h/f-tables =======================
__global__ void k_pre(const float* __restrict__ x, const float* __restrict__ Ww,
                      const float* __restrict__ Wb, const float* __restrict__ a1,
                      const float* __restrict__ a2, const float* __restrict__ ab,
                      const int* __restrict__ adj) {
    __shared__ float xs[16][NEMB];
    __shared__ float s1[16][2], s2[16][2];
    const int tid = threadIdx.x;

    if (blockIdx.x < 1024) {
        const int w = tid >> 5, lane = tid & 31;
        const int row = blockIdx.x * 8 + w;
        const int* p = adj + (size_t)row * NROWS;
        int c = 0;
        #pragma unroll 2
        for (int ch = 0; ch < 64; ch++) {
            if ((ch & 3) == 0 && lane == 0) g_cq[row * NCQ + (ch >> 2)] = c;
            unsigned b[4];
            #pragma unroll
            for (int q = 0; q < 4; q++)
                b[q] = __ballot_sync(0xffffffffu, __ldg(p + ch * 128 + q * 32 + lane) > 0);
            if (lane == 0)
                *(uint4*)(g_bits + (size_t)row * 256 + ch * 4) = make_uint4(b[0], b[1], b[2], b[3]);
            c += __popc(b[0]) + __popc(b[1]) + __popc(b[2]) + __popc(b[3]);
        }
        if (lane == 0) g_cnt[row] = c;
        return;
    }

    const int bid = blockIdx.x - 1024;
    const int r = tid >> 6, d = tid & 63;
    const int base = bid * 16;
    {
        const float4* src = (const float4*)(x + (size_t)base * NEMB);
        float4* dst = (float4*)&xs[0][0];
        #pragma unroll
        for (int t = 0; t < 4; t++) dst[tid + t * 256] = __ldg(src + tid + t * 256);
    }
    __syncthreads();

    const float wb = Wb[d];
    float acc[4] = {wb, wb, wb, wb};
    #pragma unroll 4
    for (int k = 0; k < NEMB; k++) {
        const float wv = __ldg(Ww + k * NHID + d);
        acc[0] = fmaf(xs[r][k],      wv, acc[0]);
        acc[1] = fmaf(xs[r + 4][k],  wv, acc[1]);
        acc[2] = fmaf(xs[r + 8][k],  wv, acc[2]);
        acc[3] = fmaf(xs[r + 12][k], wv, acc[3]);
    }
    const float va1 = __ldg(a1 + d), va2 = __ldg(a2 + d);
    const int half_ = (tid >> 5) & 1;
    #pragma unroll
    for (int i = 0; i < 4; i++) {
        const int k = base + r + 4 * i;
        const int pr = (k >> 4) * 8 + ((k & 15) >> 1);
        g_hp[(size_t)pr * 128 + d * 2 + (k & 1)] = __float2half_rn(acc[i]);
        float v1 = acc[i] * va1, v2 = acc[i] * va2;
        #pragma unroll
        for (int o = 16; o >= 1; o >>= 1) {
            v1 += __shfl_xor_sync(0xffffffffu, v1, o);
            v2 += __shfl_xor_sync(0xffffffffu, v2, o);
        }
        if ((tid & 31) == 0) { s1[r + 4 * i][half_] = v1; s2[r + 4 * i][half_] = v2; }
    }
    __syncthreads();
    if (tid < 16) {
        const int row = base + tid;
        float fs = s1[tid][0] + s1[tid][1] + ab[0];
        float fd = s2[tid][0] + s2[tid][1];
        g_fsp[row] = make_float2(fs, expf(fs));
        g_fdp[row] = make_float2(fd, expf(fd));
    }
}

// ======================= K2: exclusive scan of counts =======================
__global__ void k_scan() {
    __shared__ int sums[256];
    const int t = threadIdx.x;
    const int base = t * 32;
    int tot = 0;
    #pragma unroll
    for (int k = 0; k < 32; k++) tot += g_cnt[base + k];
    sums[t] = tot;
    __syncthreads();
    #pragma unroll
    for (int off = 1; off < 256; off <<= 1) {
        int u = (t >= off) ? sums[t - off] : 0;
        __syncthreads();
        sums[t] += u;
        __syncthreads();
    }
    int run = sums[t] - tot;
    #pragma unroll
    for (int k = 0; k < 32; k++) { int c = g_cnt[base + k]; g_R[base + k] = run; run += c; }
}

// ======================= K3: k_E — dense fp16 E in fragment-image layout =======================
__device__ __forceinline__ float edgeE2(int rr, int rbhi, float2 arow) {
    const int hi = rr >> 13;
    float2 a = arow;
    if (hi != rbhi) a = __ldg(&g_fsp[hi]);
    float2 bq = __ldg(&g_fdp[rr & (NROWS - 1)]);
    float s = a.x + bq.x;
    float u = 0.01f * s;
    float p = fmaf(fmaf(u, 0.5f, 1.0f), u, 1.0f);
    return (s >= 0.0f) ? a.y * bq.y : p;
}

// grid 1024 = 128 mtiles x 8 splits; warp w owns rows 8w..8w+7; no smem, no barriers.
__global__ void __launch_bounds__(256)
k_E() {
    const int tid = threadIdx.x;
    const int w = tid >> 5, lane = tid & 31;
    const int split = blockIdx.x & (NSPLIT - 1);
    const int mtile = blockIdx.x >> 3;
    const int row0 = mtile * 64;

    const int sh = 2 * (lane & 15);
    unsigned mA, mB;
    if (lane < 16) { mA = (1u << sh) - 1u; mB = 0u; }
    else           { mA = 0xFFFFFFFFu;     mB = (1u << sh) - 1u; }
    const int ch = lane >> 2;
    const int lo = (2 * lane) & 7;

    int   rank[8];
    float sacc[8];
    #pragma unroll
    for (int i = 0; i < 8; i++) {
        const int row = row0 + w * 8 + i;
        rank[i] = __ldg(&g_R[row]) + __ldg(&g_cq[row * NCQ + 2 * split]);
        sacc[i] = 0.0f;
    }

    for (int t = 0; t < NTILE; t++) {
        const int kt = split * NTILE + t;
        unsigned short* Et = g_E + (size_t)(mtile * 128 + kt) * 4096;
        #pragma unroll
        for (int i = 0; i < 8; i++) {
            const int row = w * 8 + i;
            const uint2 bw = __ldg((const uint2*)(g_bits + (size_t)(row0 + row) * 256 + 2 * kt));
            const unsigned b0 = bw.x, b1 = bw.y;
            const int rb = rank[i];
            const int rbhi = rb >> 13;
            const float2 arow = __ldg(&g_fsp[rbhi]);
            rank[i] = rb + __popc(b0) + __popc(b1);
            const int below = __popc(b0 & mA) + __popc(b1 & mB);
            const unsigned ul = (lane < 16) ? b0 : b1;
            const unsigned bb = (ul >> sh) & 3u;
            unsigned short h0 = 0, h1 = 0;
            if (bb & 1u) {
                const __half hh = __float2half_rn(edgeE2(rb + below, rbhi, arow));
                h0 = __half_as_ushort(hh); sacc[i] += __half2float(hh);
            }
            if (bb & 2u) {
                const __half hh = __float2half_rn(edgeE2(rb + below + (int)(bb & 1u), rbhi, arow));
                h1 = __half_as_ushort(hh); sacc[i] += __half2float(hh);
            }
            const int swz = row & 7;
            *(unsigned*)(Et + row * 64 + ((ch ^ swz) << 3) + lo) =
                (unsigned)h0 | ((unsigned)h1 << 16);
        }
    }

    #pragma unroll
    for (int i = 0; i < 8; i++) {
        float sv = sacc[i];
        #pragma unroll
        for (int o = 16; o >= 1; o >>= 1) sv += __shfl_xor_sync(0xffffffffu, sv, o);
        if (lane == 0) g_Sp[split * NROWS + row0 + w * 8 + i] = sv;
    }
}

// ======================= K4: streaming GEMM =======================
__device__ __forceinline__ void phaseB(unsigned afa, const __half2* __restrict__ hb,
                                       float (&acc)[4][4], int mi, int nj, int lane) {
    const int tl = lane & 3, gq = lane >> 2;
    const int r  = mi * 16 + (lane & 15);
    const int hk = lane >> 4;
    const unsigned abase = afa + r * 128;
    const int rs = r & 7;
    #pragma unroll
    for (int s = 0; s < 4; s++) {
        unsigned a0, a1, a2, a3;
        const unsigned addr = abase + ((unsigned)(((s * 2 + hk) ^ rs)) << 4);
        asm volatile("ldmatrix.sync.aligned.m8n8.x4.shared.b16 {%0,%1,%2,%3}, [%4];"
                     : "=r"(a0), "=r"(a1), "=r"(a2), "=r"(a3) : "r"(addr));
        const __half2* hp = hb + s * 8 * 72;
        const int d = nj * 32 + gq;
        #pragma unroll
        for (int n8 = 0; n8 < 4; n8++) {
            const unsigned b0 = *(const unsigned*)(hp + tl * 72 + d + n8 * 8);
            const unsigned b1 = *(const unsigned*)(hp + (tl + 4) * 72 + d + n8 * 8);
            mma_f16(acc[n8], a0, a1, a2, a3, b0, b1);
        }
    }
}

// smem: Af[3] 3x8192 | hs[3] 3x9216  = 52224 B
__global__ void __launch_bounds__(256, 4)
k_main() {
    extern __shared__ char dsm[];
    const unsigned afa0 = (unsigned)__cvta_generic_to_shared(dsm);
    const unsigned hsa0 = (unsigned)__cvta_generic_to_shared(dsm + 24576);

    const int tid  = threadIdx.x;
    const int w    = tid >> 5;
    const int lane = tid & 31;
    const int split = blockIdx.x & (NSPLIT - 1);
    const int mtile = blockIdx.x >> 3;
    const int mi = w >> 1, nj = w & 1;

    float acc[4][4];
    #pragma unroll
    for (int n = 0; n < 4; n++)
        #pragma unroll
        for (int p = 0; p < 4; p++) acc[n][p] = 0.0f;

    const int ktbase = split * NTILE;
    const int kbase  = split * KSPL;

    #define LOAD_T(T, BUF) do {                                                   \
        const char* esrc = (const char*)(g_E + (size_t)(mtile * 128 + ktbase + (T)) * 4096); \
        cpasync16(afa0 + (BUF) * 8192 + tid * 32,      esrc + tid * 32);          \
        cpasync16(afa0 + (BUF) * 8192 + tid * 32 + 16, esrc + tid * 32 + 16);     \
        const size_t rb = (size_t)((kbase + (T) * 64) >> 1);                      \
        _Pragma("unroll")                                                         \
        for (int c = 0; c < 2; c++) {                                             \
            const int id = tid + 256 * c;                                         \
            const int rr = id >> 4, oo = id & 15;                                 \
            cpasync16(hsa0 + (BUF) * 9216 + rr * 288 + oo * 16,                   \
                      (const char*)g_hp + (rb + rr) * 256 + oo * 16);             \
        }                                                                         \
        CP_COMMIT();                                                              \
    } while (0)

    // prologue: tiles 0, 1
    LOAD_T(0, 0);
    LOAD_T(1, 1);

    int cur = 0, nb = 2;
    #pragma unroll 1
    for (int t = 0; t < NTILE; t++) {
        if (t < NTILE - 1) asm volatile("cp.async.wait_group 1;" ::: "memory");
        else               asm volatile("cp.async.wait_group 0;" ::: "memory");
        __syncthreads();
        if (t + 2 < NTILE) LOAD_T(t + 2, nb);
        phaseB(afa0 + cur * 8192, (const __half2*)(dsm + 24576 + cur * 9216),
               acc, mi, nj, lane);
        cur = (cur == 2) ? 0 : cur + 1;
        nb  = (nb == 2) ? 0 : nb + 1;
    }

    // numerator partials
    {
        const int tl = lane & 3, gq = lane >> 2;
        const int grow = mtile * 64 + mi * 16 + gq;
        float* dst = g_part + ((size_t)split * NROWS + grow) * 64 + nj * 32 + tl * 2;
        #pragma unroll
        for (int n8 = 0; n8 < 4; n8++) {
            *(float2*)(dst + n8 * 8)          = make_float2(acc[n8][0], acc[n8][1]);
            *(float2*)(dst + 8 * 64 + n8 * 8) = make_float2(acc[n8][2], acc[n8][3]);
        }
    }
}

// ======================= K5: combine splits + softmax divide + elu =======================
__global__ void k_comb(float* __restrict__ out) {
    const int idx = blockIdx.x * 256 + threadIdx.x;
    const int row = idx >> 4;
    const int c4  = idx & 15;
    float4 v = make_float4(0.f, 0.f, 0.f, 0.f);
    float S = 0.f;
    #pragma unroll
    for (int s = 0; s < NSPLIT; s++) {
        const float4 p = *(const float4*)(g_part + ((size_t)s * NROWS + row) * NHID + c4 * 4);
        v.x += p.x; v.y += p.y; v.z += p.z; v.w += p.w;
        S += g_Sp[s * NROWS + row];
    }
    const float sinv = 1.0f / S;
    float o[4] = {v.x * sinv, v.y * sinv, v.z * sinv, v.w * sinv};
    #pragma unroll
    for (int c = 0; c < 4; c++) o[c] = (o[c] > 0.0f) ? o[c] : expm1f(o[c]);
    *(float4*)(out + (size_t)row * NHID + c4 * 4) = make_float4(o[0], o[1], o[2], o[3]);
}

extern "C" void kernel_launch(void* const* d_in, const int* in_sizes, int n_in,
                              void* d_out, int out_size) {
    (void)in_sizes; (void)n_in; (void)out_size;
    const float* x   = (const float*)d_in[0];
    const int*   adj = (const int*)d_in[1];
    const float* Ww  = (const float*)d_in[2];
    const float* Wb  = (const float*)d_in[3];
    const float* a1  = (const float*)d_in[4];
    const float* a2  = (const float*)d_in[5];
    const float* ab  = (const float*)d_in[6];
    float* out = (float*)d_out;

    cudaFuncSetAttribute(k_main, cudaFuncAttributeMaxDynamicSharedMemorySize, 52224);

    k_pre <<<1536, 256>>>(x, Ww, Wb, a1, a2, ab, adj);
    k_scan<<<1, 256>>>();
    k_E   <<<128 * NSPLIT, 256>>>();
    k_main<<<128 * NSPLIT, 256, 52224>>>();
    k_comb<<<NROWS * NHID / 1024, 256>>>(out);
}